// round 1
// baseline (speedup 1.0000x reference)
#include <cuda_runtime.h>

#define NX 20000
#define NL 48
#define NK 1024
#define NT 600
#define NG 12           // ell-groups of 4 (float4)
#define NSTRIPE 16      // tau stripes
#define TPB (NG * NSTRIPE)  // 192 threads

__device__ float g_Tl[NL * NK];
__device__ float g_El[NL * NK];

// ---------------------------------------------------------------------------
// Kernel 1: line-of-sight tau-integration.
// One block per k. Thread layout: eg = tid%12 (handles 4 ells via float4),
// stripe = tid/12 (tau = stripe, stripe+16, ...).
// ---------------------------------------------------------------------------
__global__ __launch_bounds__(TPB) void klos(
    const float* __restrict__ k,  const float* __restrict__ tau,
    const float* __restrict__ tau0p,
    const float* __restrict__ S0, const float* __restrict__ S1,
    const float* __restrict__ S2, const float* __restrict__ SE,
    const float* __restrict__ bx,
    const float* __restrict__ p0, const float* __restrict__ p1,
    const float* __restrict__ p2, const float* __restrict__ pe)
{
    __shared__ float sS0[NT], sS1[NT], sS2[NT], sSE[NT], stau[NT], swt[NT];
    __shared__ float red[TPB * 8];

    const int ik  = blockIdx.x;
    const int tid = threadIdx.x;

    // Stage S rows for this k + tau values + trapezoid weights.
    for (int t = tid; t < NT; t += TPB) {
        sS0[t] = S0[ik * NT + t];
        sS1[t] = S1[ik * NT + t];
        sS2[t] = S2[ik * NT + t];
        sSE[t] = SE[ik * NT + t];
        float tc = tau[t];
        stau[t] = tc;
        float tp = (t + 1 < NT) ? tau[t + 1] : tc;
        float tm = (t > 0)      ? tau[t - 1] : tc;
        swt[t] = 0.5f * (tp - tm);   // trapezoid weight
    }
    __syncthreads();

    const float kk   = k[ik];
    const float t0   = tau0p[0];
    const float xmin = bx[0];
    const float inv  = (float)(NX - 1) / (bx[NX - 1] - xmin);

    const int eg = tid % NG;
    const int st = tid / NG;
    const int co = eg * 4;     // first ell of this group

    float aT0 = 0.f, aT1 = 0.f, aT2 = 0.f, aT3 = 0.f;
    float aE0 = 0.f, aE1 = 0.f, aE2 = 0.f, aE3 = 0.f;

    for (int t = st; t < NT; t += NSTRIPE) {
        float x   = kk * (t0 - stau[t]);
        float pos = (x - xmin) * inv;
        pos = fminf(fmaxf(pos, 0.0f), (float)(NX - 1));
        int i0 = (int)pos;                 // floor (pos >= 0)
        if (i0 > NX - 2) i0 = NX - 2;
        float w  = pos - (float)i0;
        float wm = 1.0f - w;

        int b0 = i0 * NL + co;
        int b1 = b0 + NL;
        float4 A0 = *(const float4*)(p0 + b0), B0 = *(const float4*)(p0 + b1);
        float4 A1 = *(const float4*)(p1 + b0), B1 = *(const float4*)(p1 + b1);
        float4 A2 = *(const float4*)(p2 + b0), B2 = *(const float4*)(p2 + b1);
        float4 AE = *(const float4*)(pe + b0), BE = *(const float4*)(pe + b1);

        float s0 = sS0[t], s1 = sS1[t], s2 = sS2[t], se = sSE[t];
        float wq = swt[t];
        float sw0 = wq * s0, sw1 = wq * s1, sw2 = wq * s2, swe = wq * se;

        aT0 += sw0 * (A0.x * wm + B0.x * w) + sw1 * (A1.x * wm + B1.x * w) + sw2 * (A2.x * wm + B2.x * w);
        aT1 += sw0 * (A0.y * wm + B0.y * w) + sw1 * (A1.y * wm + B1.y * w) + sw2 * (A2.y * wm + B2.y * w);
        aT2 += sw0 * (A0.z * wm + B0.z * w) + sw1 * (A1.z * wm + B1.z * w) + sw2 * (A2.z * wm + B2.z * w);
        aT3 += sw0 * (A0.w * wm + B0.w * w) + sw1 * (A1.w * wm + B1.w * w) + sw2 * (A2.w * wm + B2.w * w);
        aE0 += swe * (AE.x * wm + BE.x * w);
        aE1 += swe * (AE.y * wm + BE.y * w);
        aE2 += swe * (AE.z * wm + BE.z * w);
        aE3 += swe * (AE.w * wm + BE.w * w);
    }

    float* r = red + tid * 8;
    r[0] = aT0; r[1] = aT1; r[2] = aT2; r[3] = aT3;
    r[4] = aE0; r[5] = aE1; r[6] = aE2; r[7] = aE3;
    __syncthreads();

    // 96 threads: each sums one (ellgroup, component) over the 16 stripes.
    if (tid < NG * 8) {
        int comp = tid % 8;
        int g    = tid / 8;
        float s = 0.f;
        #pragma unroll
        for (int sp = 0; sp < NSTRIPE; sp++)
            s += red[(sp * NG + g) * 8 + comp];
        int ell = g * 4 + (comp & 3);
        if (comp < 4) g_Tl[ell * NK + ik] = s;
        else          g_El[ell * NK + ik] = s;
    }
}

// ---------------------------------------------------------------------------
// Kernel 2: k-integration -> Cl. One block per ell.
// ---------------------------------------------------------------------------
__global__ __launch_bounds__(256) void kcl(
    const float* __restrict__ k,
    const float* __restrict__ Asp, const float* __restrict__ nsp,
    float* __restrict__ out)
{
    const int ell = blockIdx.x;
    const int tid = threadIdx.x;
    const float A_s = Asp[0];
    const float n_s = nsp[0];
    const float PI  = 3.14159265358979323846f;

    float sTT = 0.f, sEE = 0.f, sTE = 0.f;
    for (int i = tid; i < NK; i += 256) {
        float kk = k[i];
        float kp = (i + 1 < NK) ? k[i + 1] : kk;
        float km = (i > 0)      ? k[i - 1] : kk;
        float wt = 0.5f * (kp - km);
        // P_R = A_s (k/kp)^(ns-1) * 2 pi^2 / k^3 ; w = k^2 * P_R
        float pr = A_s * powf(kk * (1.0f / 0.05f), n_s - 1.0f)
                       * (2.0f * PI * PI / (kk * kk * kk));
        float w  = kk * kk * pr;
        float wtw = wt * w;
        float T = g_Tl[ell * NK + i];
        float E = g_El[ell * NK + i];
        sTT += wtw * T * T;
        sEE += wtw * E * E;
        sTE += wtw * T * E;
    }

    __shared__ float sh0[256], sh1[256], sh2[256];
    sh0[tid] = sTT; sh1[tid] = sEE; sh2[tid] = sTE;
    __syncthreads();
    for (int s = 128; s > 0; s >>= 1) {
        if (tid < s) {
            sh0[tid] += sh0[tid + s];
            sh1[tid] += sh1[tid + s];
            sh2[tid] += sh2[tid + s];
        }
        __syncthreads();
    }
    if (tid == 0) {
        const float c = 2.0f / PI;
        out[0 * NL + ell] = c * sh0[0];
        out[1 * NL + ell] = c * sh1[0];
        out[2 * NL + ell] = c * sh2[0];
    }
}

// ---------------------------------------------------------------------------
extern "C" void kernel_launch(void* const* d_in, const int* in_sizes, int n_in,
                              void* d_out, int out_size)
{
    const float* k    = (const float*)d_in[0];
    const float* tau  = (const float*)d_in[1];
    const float* tau0 = (const float*)d_in[2];
    const float* S0   = (const float*)d_in[3];
    const float* S1   = (const float*)d_in[4];
    const float* S2   = (const float*)d_in[5];
    const float* SE   = (const float*)d_in[6];
    const float* bx   = (const float*)d_in[7];
    const float* p0   = (const float*)d_in[8];
    const float* p1   = (const float*)d_in[9];
    const float* p2   = (const float*)d_in[10];
    const float* pe   = (const float*)d_in[11];
    const float* A_s  = (const float*)d_in[12];
    const float* n_s  = (const float*)d_in[13];
    float* out = (float*)d_out;

    klos<<<NK, TPB>>>(k, tau, tau0, S0, S1, S2, SE, bx, p0, p1, p2, pe);
    kcl<<<NL, 256>>>(k, A_s, n_s, out);
}

// round 2
// speedup vs baseline: 1.1946x; 1.1946x over previous
#include <cuda_runtime.h>

#define NX 20000
#define NL 48
#define NK 1024
#define NT 600
#define NSTRIPE 8
#define NQ 48                 // (table, ell-group-of-4) pairs: 4 tables x 12 groups
#define TPB (NQ * NSTRIPE)    // 384 threads

// Combined table: C[x][tbl*48 + ell], 192 floats (768B) per x-row, aligned.
__device__ float g_C[NX * 192];
__device__ float g_T[NL * NK];   // scaled transfer functions
__device__ float g_E[NL * NK];

// ---------------------------------------------------------------------------
// Kernel 0: pack the four [NX, NL] tables into one [NX, 192] combined table.
// ---------------------------------------------------------------------------
__global__ __launch_bounds__(256) void kpack(
    const float* __restrict__ p0, const float* __restrict__ p1,
    const float* __restrict__ p2, const float* __restrict__ pe)
{
    int i = blockIdx.x * 256 + threadIdx.x;       // over NX*NL
    if (i < NX * NL) {
        int x = i / NL, ell = i % NL;
        int o = x * 192 + ell;
        g_C[o      ] = p0[i];
        g_C[o +  48] = p1[i];
        g_C[o +  96] = p2[i];
        g_C[o + 144] = pe[i];
    }
}

// ---------------------------------------------------------------------------
// Kernel 1: line-of-sight tau-integration. One block per k.
// Thread layout: tid = st*48 + q; q = tbl*12 + eg; thread handles 4 ells
// (float4) of one table, tau stripe st. Warp lanes cover 512B contiguous.
// ---------------------------------------------------------------------------
__global__ __launch_bounds__(TPB) void klos(
    const float* __restrict__ k,  const float* __restrict__ tau,
    const float* __restrict__ tau0p, const float* __restrict__ bx,
    const float* __restrict__ S0, const float* __restrict__ S1,
    const float* __restrict__ S2, const float* __restrict__ SE,
    const float* __restrict__ Asp, const float* __restrict__ nsp)
{
    __shared__ float sSw[4 * NT];   // S_tbl[t] * trapezoid weight
    __shared__ float swf[NT];       // interp fractional weight
    __shared__ int   si0[NT];       // i0 * 192 (pre-scaled row offset)
    __shared__ float red[TPB * 4];
    __shared__ float sscale;

    const int ik  = blockIdx.x;
    const int tid = threadIdx.x;

    const float kk   = k[ik];
    const float t0   = tau0p[0];
    const float xmin = bx[0];
    const float inv  = (float)(NX - 1) / (bx[NX - 1] - xmin);

    for (int t = tid; t < NT; t += TPB) {
        float tc = tau[t];
        float tp = (t + 1 < NT) ? tau[t + 1] : tc;
        float tm = (t > 0)      ? tau[t - 1] : tc;
        float wt = 0.5f * (tp - tm);
        sSw[0 * NT + t] = S0[ik * NT + t] * wt;
        sSw[1 * NT + t] = S1[ik * NT + t] * wt;
        sSw[2 * NT + t] = S2[ik * NT + t] * wt;
        sSw[3 * NT + t] = SE[ik * NT + t] * wt;
        float pos = (kk * (t0 - tc) - xmin) * inv;
        pos = fminf(fmaxf(pos, 0.0f), (float)(NX - 1));
        int i0 = (int)pos;
        if (i0 > NX - 2) i0 = NX - 2;
        swf[t] = pos - (float)i0;
        si0[t] = i0 * 192;
    }
    if (tid == 0) {
        // fold sqrt( (2/pi) * dk * k^2 * P_R(k) ) into T,E
        float kp = (ik + 1 < NK) ? k[ik + 1] : kk;
        float km = (ik > 0)      ? k[ik - 1] : kk;
        float dk = 0.5f * (kp - km);
        const float PI = 3.14159265358979323846f;
        float A_s = Asp[0], n_s = nsp[0];
        float pr = A_s * powf(kk * 20.0f, n_s - 1.0f)
                       * (2.0f * PI * PI / (kk * kk * kk));
        float w  = kk * kk * pr;                    // k^2 P_R
        sscale = sqrtf((2.0f / PI) * dk * w);
    }
    __syncthreads();

    const int q  = tid % NQ;
    const int st = tid / NQ;
    const int tbl = q / 12;
    const float* __restrict__ srow = sSw + tbl * NT;
    const int qo = q * 4;

    float a0 = 0.f, a1 = 0.f, a2 = 0.f, a3 = 0.f;

    for (int t = st; t < NT; t += NSTRIPE) {
        int   b = si0[t] + qo;
        float w = swf[t];
        float4 A = *(const float4*)(g_C + b);
        float4 B = *(const float4*)(g_C + b + 192);
        float c = srow[t];
        a0 += c * fmaf(w, B.x - A.x, A.x);
        a1 += c * fmaf(w, B.y - A.y, A.y);
        a2 += c * fmaf(w, B.z - A.z, A.z);
        a3 += c * fmaf(w, B.w - A.w, A.w);
    }

    float* r = red + tid * 4;
    r[0] = a0; r[1] = a1; r[2] = a2; r[3] = a3;
    __syncthreads();

    // 96 threads produce outputs: tid<48 -> T[ell] (sum tables 0..2 over stripes),
    // tid in [48,96) -> E[ell] (table 3 over stripes).
    if (tid < 96) {
        int ell = tid % NL;
        int eg  = ell >> 2;
        int j   = ell & 3;
        float s = 0.f;
        if (tid < 48) {
            #pragma unroll
            for (int sp = 0; sp < NSTRIPE; sp++)
                #pragma unroll
                for (int tb = 0; tb < 3; tb++)
                    s += red[(sp * NQ + tb * 12 + eg) * 4 + j];
            g_T[ell * NK + ik] = s * sscale;
        } else {
            #pragma unroll
            for (int sp = 0; sp < NSTRIPE; sp++)
                s += red[(sp * NQ + 36 + eg) * 4 + j];
            g_E[ell * NK + ik] = s * sscale;
        }
    }
}

// ---------------------------------------------------------------------------
// Kernel 2: k-reduction. One block per ell, float4 loads, weights already
// folded into g_T/g_E.
// ---------------------------------------------------------------------------
__global__ __launch_bounds__(256) void kcl(float* __restrict__ out)
{
    const int ell = blockIdx.x;
    const int tid = threadIdx.x;

    float4 T = ((const float4*)(g_T + ell * NK))[tid];
    float4 E = ((const float4*)(g_E + ell * NK))[tid];
    float tt = T.x*T.x + T.y*T.y + T.z*T.z + T.w*T.w;
    float ee = E.x*E.x + E.y*E.y + E.z*E.z + E.w*E.w;
    float te = T.x*E.x + T.y*E.y + T.z*E.z + T.w*E.w;

    #pragma unroll
    for (int o = 16; o > 0; o >>= 1) {
        tt += __shfl_xor_sync(0xffffffffu, tt, o);
        ee += __shfl_xor_sync(0xffffffffu, ee, o);
        te += __shfl_xor_sync(0xffffffffu, te, o);
    }
    __shared__ float sh[3][8];
    int wid = tid >> 5, lid = tid & 31;
    if (lid == 0) { sh[0][wid] = tt; sh[1][wid] = ee; sh[2][wid] = te; }
    __syncthreads();
    if (tid == 0) {
        float s0 = 0.f, s1 = 0.f, s2 = 0.f;
        #pragma unroll
        for (int wv = 0; wv < 8; wv++) { s0 += sh[0][wv]; s1 += sh[1][wv]; s2 += sh[2][wv]; }
        out[0 * NL + ell] = s0;
        out[1 * NL + ell] = s1;
        out[2 * NL + ell] = s2;
    }
}

// ---------------------------------------------------------------------------
extern "C" void kernel_launch(void* const* d_in, const int* in_sizes, int n_in,
                              void* d_out, int out_size)
{
    const float* k    = (const float*)d_in[0];
    const float* tau  = (const float*)d_in[1];
    const float* tau0 = (const float*)d_in[2];
    const float* S0   = (const float*)d_in[3];
    const float* S1   = (const float*)d_in[4];
    const float* S2   = (const float*)d_in[5];
    const float* SE   = (const float*)d_in[6];
    const float* bx   = (const float*)d_in[7];
    const float* p0   = (const float*)d_in[8];
    const float* p1   = (const float*)d_in[9];
    const float* p2   = (const float*)d_in[10];
    const float* pe   = (const float*)d_in[11];
    const float* A_s  = (const float*)d_in[12];
    const float* n_s  = (const float*)d_in[13];
    float* out = (float*)d_out;

    kpack<<<(NX * NL + 255) / 256, 256>>>(p0, p1, p2, pe);
    klos<<<NK, TPB>>>(k, tau, tau0, bx, S0, S1, S2, SE, A_s, n_s);
    kcl<<<NL, 256>>>(out);
}

// round 3
// speedup vs baseline: 1.4094x; 1.1798x over previous
#include <cuda_runtime.h>
#include <cuda_fp16.h>

#define NX 20000
#define NL 48
#define NK 1024
#define NT 600
#define NSTRIPE 8
#define NQ 48                 // (table, ell-group-of-4) pairs: 4 tables x 12 groups
#define TPB (NQ * NSTRIPE)    // 384 threads

// Combined fp16 table: Ch[x][tbl*48 + ell], 192 halves (384B) per x-row.
__device__ __half g_Ch[NX * 192];
__device__ float  g_T[NL * NK];   // weight-folded transfer functions
__device__ float  g_E[NL * NK];

// ---------------------------------------------------------------------------
// Kernel 0: pack the four [NX, NL] fp32 tables into one [NX, 192] fp16 table.
// One thread per (x, ell-group-of-4): 4x float4 read, 4x 8B write.
// ---------------------------------------------------------------------------
__global__ __launch_bounds__(256) void kpack(
    const float* __restrict__ p0, const float* __restrict__ p1,
    const float* __restrict__ p2, const float* __restrict__ pe)
{
    int i = blockIdx.x * 256 + threadIdx.x;       // over NX*12
    if (i >= NX * 12) return;
    int x = i / 12, eg = i % 12;
    int src = x * NL + eg * 4;
    __half* dst = g_Ch + x * 192 + eg * 4;

    float4 v0 = *(const float4*)(p0 + src);
    float4 v1 = *(const float4*)(p1 + src);
    float4 v2 = *(const float4*)(p2 + src);
    float4 ve = *(const float4*)(pe + src);

    ((__half2*)(dst      ))[0] = __floats2half2_rn(v0.x, v0.y);
    ((__half2*)(dst      ))[1] = __floats2half2_rn(v0.z, v0.w);
    ((__half2*)(dst +  48))[0] = __floats2half2_rn(v1.x, v1.y);
    ((__half2*)(dst +  48))[1] = __floats2half2_rn(v1.z, v1.w);
    ((__half2*)(dst +  96))[0] = __floats2half2_rn(v2.x, v2.y);
    ((__half2*)(dst +  96))[1] = __floats2half2_rn(v2.z, v2.w);
    ((__half2*)(dst + 144))[0] = __floats2half2_rn(ve.x, ve.y);
    ((__half2*)(dst + 144))[1] = __floats2half2_rn(ve.z, ve.w);
}

// ---------------------------------------------------------------------------
// Kernel 1: line-of-sight tau-integration. One block per k.
// tid = st*48 + q; q = tbl*12 + eg; each thread: 4 ells of one table,
// tau stripe st. Warp lanes cover 256B contiguous fp16.
// ---------------------------------------------------------------------------
__global__ __launch_bounds__(TPB) void klos(
    const float* __restrict__ k,  const float* __restrict__ tau,
    const float* __restrict__ tau0p, const float* __restrict__ bx,
    const float* __restrict__ S0, const float* __restrict__ S1,
    const float* __restrict__ S2, const float* __restrict__ SE,
    const float* __restrict__ Asp, const float* __restrict__ nsp)
{
    __shared__ float sSw[4 * NT];   // S_tbl[t] * trapezoid weight
    __shared__ int2  siw[NT];       // {i0*192, bits(frac w)}
    __shared__ float red[TPB * 4];
    __shared__ float sscale;

    const int ik  = blockIdx.x;
    const int tid = threadIdx.x;

    const float kk   = k[ik];
    const float t0   = tau0p[0];
    const float xmin = bx[0];
    const float inv  = (float)(NX - 1) / (bx[NX - 1] - xmin);

    for (int t = tid; t < NT; t += TPB) {
        float tc = tau[t];
        float tp = (t + 1 < NT) ? tau[t + 1] : tc;
        float tm = (t > 0)      ? tau[t - 1] : tc;
        float wt = 0.5f * (tp - tm);
        sSw[0 * NT + t] = S0[ik * NT + t] * wt;
        sSw[1 * NT + t] = S1[ik * NT + t] * wt;
        sSw[2 * NT + t] = S2[ik * NT + t] * wt;
        sSw[3 * NT + t] = SE[ik * NT + t] * wt;
        float pos = (kk * (t0 - tc) - xmin) * inv;
        pos = fminf(fmaxf(pos, 0.0f), (float)(NX - 1));
        int i0 = (int)pos;
        if (i0 > NX - 2) i0 = NX - 2;
        siw[t] = make_int2(i0 * 192, __float_as_int(pos - (float)i0));
    }
    if (tid == 0) {
        // fold sqrt( (2/pi) * dk * k^2 * P_R(k) ) into T,E
        float kp = (ik + 1 < NK) ? k[ik + 1] : kk;
        float km = (ik > 0)      ? k[ik - 1] : kk;
        float dk = 0.5f * (kp - km);
        const float PI = 3.14159265358979323846f;
        float A_s = Asp[0], n_s = nsp[0];
        float pr = A_s * powf(kk * 20.0f, n_s - 1.0f)
                       * (2.0f * PI * PI / (kk * kk * kk));
        sscale = sqrtf((2.0f / PI) * dk * kk * kk * pr);
    }
    __syncthreads();

    const int q  = tid % NQ;
    const int st = tid / NQ;
    const int tbl = q / 12;
    const float* __restrict__ srow = sSw + tbl * NT;
    const int qo = q * 4;      // half-element offset

    float a0 = 0.f, a1 = 0.f, a2 = 0.f, a3 = 0.f;

    for (int t = st; t < NT; t += NSTRIPE) {
        int2  iw = siw[t];
        int   b  = iw.x + qo;
        float w  = __int_as_float(iw.y);
        __half2 wh = __float2half2_rn(w);

        const __half2* pa = (const __half2*)(g_Ch + b);
        const __half2* pb = (const __half2*)(g_Ch + b + 192);
        __half2 A01 = pa[0], A23 = pa[1];
        __half2 B01 = pb[0], B23 = pb[1];

        __half2 r01 = __hfma2(__hsub2(B01, A01), wh, A01);
        __half2 r23 = __hfma2(__hsub2(B23, A23), wh, A23);
        float2 f01 = __half22float2(r01);
        float2 f23 = __half22float2(r23);

        float c = srow[t];
        a0 = fmaf(c, f01.x, a0);
        a1 = fmaf(c, f01.y, a1);
        a2 = fmaf(c, f23.x, a2);
        a3 = fmaf(c, f23.y, a3);
    }

    float* r = red + tid * 4;
    r[0] = a0; r[1] = a1; r[2] = a2; r[3] = a3;
    __syncthreads();

    // 96 threads: tid<48 -> T[ell] (tables 0..2), tid in [48,96) -> E[ell].
    if (tid < 96) {
        int ell = tid % NL;
        int eg  = ell >> 2;
        int j   = ell & 3;
        float s = 0.f;
        if (tid < 48) {
            #pragma unroll
            for (int sp = 0; sp < NSTRIPE; sp++)
                #pragma unroll
                for (int tb = 0; tb < 3; tb++)
                    s += red[(sp * NQ + tb * 12 + eg) * 4 + j];
            g_T[ell * NK + ik] = s * sscale;
        } else {
            #pragma unroll
            for (int sp = 0; sp < NSTRIPE; sp++)
                s += red[(sp * NQ + 36 + eg) * 4 + j];
            g_E[ell * NK + ik] = s * sscale;
        }
    }
}

// ---------------------------------------------------------------------------
// Kernel 2: k-reduction. One block per ell; weights already folded.
// ---------------------------------------------------------------------------
__global__ __launch_bounds__(256) void kcl(float* __restrict__ out)
{
    const int ell = blockIdx.x;
    const int tid = threadIdx.x;

    float4 T = ((const float4*)(g_T + ell * NK))[tid];
    float4 E = ((const float4*)(g_E + ell * NK))[tid];
    float tt = T.x*T.x + T.y*T.y + T.z*T.z + T.w*T.w;
    float ee = E.x*E.x + E.y*E.y + E.z*E.z + E.w*E.w;
    float te = T.x*E.x + T.y*E.y + T.z*E.z + T.w*E.w;

    #pragma unroll
    for (int o = 16; o > 0; o >>= 1) {
        tt += __shfl_xor_sync(0xffffffffu, tt, o);
        ee += __shfl_xor_sync(0xffffffffu, ee, o);
        te += __shfl_xor_sync(0xffffffffu, te, o);
    }
    __shared__ float sh[3][8];
    int wid = tid >> 5, lid = tid & 31;
    if (lid == 0) { sh[0][wid] = tt; sh[1][wid] = ee; sh[2][wid] = te; }
    __syncthreads();
    if (tid == 0) {
        float s0 = 0.f, s1 = 0.f, s2 = 0.f;
        #pragma unroll
        for (int wv = 0; wv < 8; wv++) { s0 += sh[0][wv]; s1 += sh[1][wv]; s2 += sh[2][wv]; }
        out[0 * NL + ell] = s0;
        out[1 * NL + ell] = s1;
        out[2 * NL + ell] = s2;
    }
}

// ---------------------------------------------------------------------------
extern "C" void kernel_launch(void* const* d_in, const int* in_sizes, int n_in,
                              void* d_out, int out_size)
{
    const float* k    = (const float*)d_in[0];
    const float* tau  = (const float*)d_in[1];
    const float* tau0 = (const float*)d_in[2];
    const float* S0   = (const float*)d_in[3];
    const float* S1   = (const float*)d_in[4];
    const float* S2   = (const float*)d_in[5];
    const float* SE   = (const float*)d_in[6];
    const float* bx   = (const float*)d_in[7];
    const float* p0   = (const float*)d_in[8];
    const float* p1   = (const float*)d_in[9];
    const float* p2   = (const float*)d_in[10];
    const float* pe   = (const float*)d_in[11];
    const float* A_s  = (const float*)d_in[12];
    const float* n_s  = (const float*)d_in[13];
    float* out = (float*)d_out;

    kpack<<<(NX * 12 + 255) / 256, 256>>>(p0, p1, p2, pe);
    klos<<<NK, TPB>>>(k, tau, tau0, bx, S0, S1, S2, SE, A_s, n_s);
    kcl<<<NL, 256>>>(out);
}

// round 6
// speedup vs baseline: 1.8049x; 1.2806x over previous
#include <cuda_runtime.h>
#include <cuda_fp16.h>

#define NX 20000
#define NL 48
#define NK 1024
#define NT 600
#define NSTRIPE 16
#define NQ 24                 // (table, ell-group-of-8): 4 tables x 6 groups
#define TPB (NQ * NSTRIPE)    // 384 threads

// Combined fp16 table: Ch[x][tbl*48 + ell], 192 halves (384B) per x-row.
__device__ __half g_Ch[NX * 192];

// Bit-cast helpers (no SASS cost).
static __device__ __forceinline__ int h2_as_int(__half2 h) {
    return *reinterpret_cast<int*>(&h);
}
static __device__ __forceinline__ __half2 int_as_h2(int i) {
    return *reinterpret_cast<__half2*>(&i);
}

// ---------------------------------------------------------------------------
// Kernel Z: zero the output (re-runs every graph replay, before the atomics).
// ---------------------------------------------------------------------------
__global__ void kzero(float* __restrict__ out)
{
    out[threadIdx.x] = 0.0f;   // 144 threads
}

// ---------------------------------------------------------------------------
// Kernel 0: pack the four [NX, NL] fp32 tables into one [NX, 192] fp16 table.
// One thread per (x, ell-group-of-8): per table 2x float4 read, 1x int4 write.
// ---------------------------------------------------------------------------
__global__ __launch_bounds__(256) void kpack(
    const float* __restrict__ p0, const float* __restrict__ p1,
    const float* __restrict__ p2, const float* __restrict__ pe)
{
    int i = blockIdx.x * 256 + threadIdx.x;       // over NX*6
    if (i >= NX * 6) return;
    int x = i / 6, eg = i % 6;
    int src = x * NL + eg * 8;
    __half* dst = g_Ch + x * 192 + eg * 8;

    const float* ps[4] = { p0, p1, p2, pe };
    #pragma unroll
    for (int tb = 0; tb < 4; tb++) {
        float4 va = *(const float4*)(ps[tb] + src);
        float4 vb = *(const float4*)(ps[tb] + src + 4);
        int4 pk;
        pk.x = h2_as_int(__floats2half2_rn(va.x, va.y));
        pk.y = h2_as_int(__floats2half2_rn(va.z, va.w));
        pk.z = h2_as_int(__floats2half2_rn(vb.x, vb.y));
        pk.w = h2_as_int(__floats2half2_rn(vb.z, vb.w));
        *(int4*)(dst + tb * 48) = pk;
    }
}

// ---------------------------------------------------------------------------
// Kernel 1: line-of-sight tau-integration + Cl accumulation. One block per k.
// tid = st*24 + q; q = tbl*6 + g; thread handles 8 ells (one LDG.128 per row)
// of one table, tau stripe st. A warp's 24 q-lanes cover one full 384B row.
// ---------------------------------------------------------------------------
__global__ __launch_bounds__(TPB) void klos(
    const float* __restrict__ k,  const float* __restrict__ tau,
    const float* __restrict__ tau0p, const float* __restrict__ bx,
    const float* __restrict__ S0, const float* __restrict__ S1,
    const float* __restrict__ S2, const float* __restrict__ SE,
    const float* __restrict__ Asp, const float* __restrict__ nsp,
    float* __restrict__ out)
{
    __shared__ float sSw[4 * NT];   // S_tbl[t] * trapezoid weight
    __shared__ int2  siw[NT];       // {i0*192, bits(frac w)}
    __shared__ float red[TPB * 8];
    __shared__ float sscale;

    const int ik  = blockIdx.x;
    const int tid = threadIdx.x;

    const float kk   = k[ik];
    const float t0   = tau0p[0];
    const float xmin = bx[0];
    const float inv  = (float)(NX - 1) / (bx[NX - 1] - xmin);

    for (int t = tid; t < NT; t += TPB) {
        float tc = tau[t];
        float tp = (t + 1 < NT) ? tau[t + 1] : tc;
        float tm = (t > 0)      ? tau[t - 1] : tc;
        float wt = 0.5f * (tp - tm);
        sSw[0 * NT + t] = S0[ik * NT + t] * wt;
        sSw[1 * NT + t] = S1[ik * NT + t] * wt;
        sSw[2 * NT + t] = S2[ik * NT + t] * wt;
        sSw[3 * NT + t] = SE[ik * NT + t] * wt;
        float pos = (kk * (t0 - tc) - xmin) * inv;
        pos = fminf(fmaxf(pos, 0.0f), (float)(NX - 1));
        int i0 = (int)pos;
        if (i0 > NX - 2) i0 = NX - 2;
        siw[t] = make_int2(i0 * 192, __float_as_int(pos - (float)i0));
    }
    if (tid == 0) {
        // sqrt( (2/pi) * dk * k^2 * P_R(k) ), folded into T,E
        float kp = (ik + 1 < NK) ? k[ik + 1] : kk;
        float km = (ik > 0)      ? k[ik - 1] : kk;
        float dk = 0.5f * (kp - km);
        const float PI = 3.14159265358979323846f;
        float A_s = Asp[0], n_s = nsp[0];
        float pr = A_s * powf(kk * 20.0f, n_s - 1.0f)
                       * (2.0f * PI * PI / (kk * kk * kk));
        sscale = sqrtf((2.0f / PI) * dk * kk * kk * pr);
    }
    __syncthreads();

    const int q   = tid % NQ;
    const int st  = tid / NQ;
    const int tbl = q / 6;
    const float* __restrict__ srow = sSw + tbl * NT;
    const int qo = q * 8;      // half-element offset (16B aligned)

    float a0=0.f,a1=0.f,a2=0.f,a3=0.f,a4=0.f,a5=0.f,a6=0.f,a7=0.f;

    #pragma unroll 2
    for (int t = st; t < NT; t += NSTRIPE) {
        int2  iw = siw[t];
        float w  = __int_as_float(iw.y);
        __half2 wh = __float2half2_rn(w);

        const int4* pa = (const int4*)(g_Ch + iw.x + qo);
        int4 Ar = pa[0];
        int4 Br = pa[24];      // next x-row: +192 halves = +384B = +24 int4

        __half2 A0 = int_as_h2(Ar.x), A1 = int_as_h2(Ar.y),
                A2 = int_as_h2(Ar.z), A3 = int_as_h2(Ar.w);
        __half2 B0 = int_as_h2(Br.x), B1 = int_as_h2(Br.y),
                B2 = int_as_h2(Br.z), B3 = int_as_h2(Br.w);

        __half2 r0 = __hfma2(__hsub2(B0, A0), wh, A0);
        __half2 r1 = __hfma2(__hsub2(B1, A1), wh, A1);
        __half2 r2 = __hfma2(__hsub2(B2, A2), wh, A2);
        __half2 r3 = __hfma2(__hsub2(B3, A3), wh, A3);

        float2 f0 = __half22float2(r0);
        float2 f1 = __half22float2(r1);
        float2 f2 = __half22float2(r2);
        float2 f3 = __half22float2(r3);

        float c = srow[t];
        a0 = fmaf(c, f0.x, a0); a1 = fmaf(c, f0.y, a1);
        a2 = fmaf(c, f1.x, a2); a3 = fmaf(c, f1.y, a3);
        a4 = fmaf(c, f2.x, a4); a5 = fmaf(c, f2.y, a5);
        a6 = fmaf(c, f3.x, a6); a7 = fmaf(c, f3.y, a7);
    }

    float* r = red + tid * 8;
    r[0]=a0; r[1]=a1; r[2]=a2; r[3]=a3; r[4]=a4; r[5]=a5; r[6]=a6; r[7]=a7;
    __syncthreads();

    // 48 threads: thread ell sums its T (tables 0..2) and E (table 3) over
    // all stripes, scales, and accumulates Cl terms atomically.
    if (tid < NL) {
        int ell = tid;
        int g   = ell >> 3;
        int j   = ell & 7;
        float sT = 0.f, sE = 0.f;
        #pragma unroll
        for (int sp = 0; sp < NSTRIPE; sp++) {
            const float* base = red + (sp * NQ) * 8 + j;
            sT += base[(0 * 6 + g) * 8] + base[(1 * 6 + g) * 8] + base[(2 * 6 + g) * 8];
            sE += base[(3 * 6 + g) * 8];
        }
        float sc = sscale;
        float T = sT * sc, E = sE * sc;
        atomicAdd(&out[0 * NL + ell], T * T);
        atomicAdd(&out[1 * NL + ell], E * E);
        atomicAdd(&out[2 * NL + ell], T * E);
    }
}

// ---------------------------------------------------------------------------
extern "C" void kernel_launch(void* const* d_in, const int* in_sizes, int n_in,
                              void* d_out, int out_size)
{
    const float* k    = (const float*)d_in[0];
    const float* tau  = (const float*)d_in[1];
    const float* tau0 = (const float*)d_in[2];
    const float* S0   = (const float*)d_in[3];
    const float* S1   = (const float*)d_in[4];
    const float* S2   = (const float*)d_in[5];
    const float* SE   = (const float*)d_in[6];
    const float* bx   = (const float*)d_in[7];
    const float* p0   = (const float*)d_in[8];
    const float* p1   = (const float*)d_in[9];
    const float* p2   = (const float*)d_in[10];
    const float* pe   = (const float*)d_in[11];
    const float* A_s  = (const float*)d_in[12];
    const float* n_s  = (const float*)d_in[13];
    float* out = (float*)d_out;

    kzero<<<1, 3 * NL>>>(out);
    kpack<<<(NX * 6 + 255) / 256, 256>>>(p0, p1, p2, pe);
    klos<<<NK, TPB>>>(k, tau, tau0, bx, S0, S1, S2, SE, A_s, n_s, out);
}

// round 7
// speedup vs baseline: 1.9151x; 1.0611x over previous
#include <cuda_runtime.h>
#include <cuda_fp16.h>

#define NX 20000
#define NL 48
#define NK 1024
#define NT 600
#define NSTRIPE 16
#define NQ 24                 // (table, ell-group-of-8): 4 tables x 6 groups
#define TPB (NQ * NSTRIPE)    // 384 threads

// Combined fp16 table: Ch[x][tbl*48 + ell], 192 halves (384B) per x-row.
__device__ __half g_Ch[NX * 192];

// Bit-cast helpers (no SASS cost).
static __device__ __forceinline__ int h2_as_int(__half2 h) {
    return *reinterpret_cast<int*>(&h);
}
static __device__ __forceinline__ __half2 int_as_h2(int i) {
    return *reinterpret_cast<__half2*>(&i);
}

// ---------------------------------------------------------------------------
// Kernel 0: pack four [NX, NL] fp32 tables into one [NX, 192] fp16 table,
// AND zero the (poisoned / previously-accumulated) output.
// One thread per (x, table, ell-group-of-8): 2x LDG.128 + 1x STG.128.
// NX*24 = 480000 = 1875 * 256 exactly.
// ---------------------------------------------------------------------------
__global__ __launch_bounds__(256) void kpack(
    const float* __restrict__ p0, const float* __restrict__ p1,
    const float* __restrict__ p2, const float* __restrict__ pe,
    float* __restrict__ out)
{
    // Block 0 also zeroes the 144-element output (completes before klos runs).
    if (blockIdx.x == 0 && threadIdx.x < 3 * NL)
        out[threadIdx.x] = 0.0f;

    int i = blockIdx.x * 256 + threadIdx.x;       // over NX*24
    int x   = i / 24;
    int sub = i % 24;
    int tbl = sub / 6;
    int eg  = sub % 6;

    const float* src = (tbl == 0 ? p0 : tbl == 1 ? p1 : tbl == 2 ? p2 : pe)
                       + x * NL + eg * 8;
    float4 va = *(const float4*)(src);
    float4 vb = *(const float4*)(src + 4);

    int4 pk;
    pk.x = h2_as_int(__floats2half2_rn(va.x, va.y));
    pk.y = h2_as_int(__floats2half2_rn(va.z, va.w));
    pk.z = h2_as_int(__floats2half2_rn(vb.x, vb.y));
    pk.w = h2_as_int(__floats2half2_rn(vb.z, vb.w));
    *(int4*)(g_Ch + x * 192 + tbl * 48 + eg * 8) = pk;
}

// ---------------------------------------------------------------------------
// Kernel 1: line-of-sight tau-integration + Cl accumulation. One block per k.
// tid = st*24 + q; q = tbl*6 + g; thread handles 8 ells (one LDG.128 per row)
// of one table, tau stripe st. A warp's 24 q-lanes cover one full 384B row.
// ---------------------------------------------------------------------------
__global__ __launch_bounds__(TPB) void klos(
    const float* __restrict__ k,  const float* __restrict__ tau,
    const float* __restrict__ tau0p, const float* __restrict__ bx,
    const float* __restrict__ S0, const float* __restrict__ S1,
    const float* __restrict__ S2, const float* __restrict__ SE,
    const float* __restrict__ Asp, const float* __restrict__ nsp,
    float* __restrict__ out)
{
    __shared__ float sSw[4 * NT];   // S_tbl[t] * trapezoid weight
    __shared__ int2  siw[NT];       // {i0*192, bits(frac w)}
    __shared__ float red[TPB * 8];
    __shared__ float sscale;

    const int ik  = blockIdx.x;
    const int tid = threadIdx.x;

    const float kk   = k[ik];
    const float t0   = tau0p[0];
    const float xmin = bx[0];
    const float inv  = (float)(NX - 1) / (bx[NX - 1] - xmin);

    for (int t = tid; t < NT; t += TPB) {
        float tc = tau[t];
        float tp = (t + 1 < NT) ? tau[t + 1] : tc;
        float tm = (t > 0)      ? tau[t - 1] : tc;
        float wt = 0.5f * (tp - tm);
        sSw[0 * NT + t] = S0[ik * NT + t] * wt;
        sSw[1 * NT + t] = S1[ik * NT + t] * wt;
        sSw[2 * NT + t] = S2[ik * NT + t] * wt;
        sSw[3 * NT + t] = SE[ik * NT + t] * wt;
        float pos = (kk * (t0 - tc) - xmin) * inv;
        pos = fminf(fmaxf(pos, 0.0f), (float)(NX - 1));
        int i0 = (int)pos;
        if (i0 > NX - 2) i0 = NX - 2;
        siw[t] = make_int2(i0 * 192, __float_as_int(pos - (float)i0));
    }
    if (tid == 0) {
        // sqrt( (2/pi) * dk * k^2 * P_R(k) ), folded into T,E
        float kp = (ik + 1 < NK) ? k[ik + 1] : kk;
        float km = (ik > 0)      ? k[ik - 1] : kk;
        float dk = 0.5f * (kp - km);
        const float PI = 3.14159265358979323846f;
        float A_s = Asp[0], n_s = nsp[0];
        float pr = A_s * powf(kk * 20.0f, n_s - 1.0f)
                       * (2.0f * PI * PI / (kk * kk * kk));
        sscale = sqrtf((2.0f / PI) * dk * kk * kk * pr);
    }
    __syncthreads();

    const int q   = tid % NQ;
    const int st  = tid / NQ;
    const int tbl = q / 6;
    const float* __restrict__ srow = sSw + tbl * NT;
    const int qo = q * 8;      // half-element offset (16B aligned)

    float a0=0.f,a1=0.f,a2=0.f,a3=0.f,a4=0.f,a5=0.f,a6=0.f,a7=0.f;

    #pragma unroll 4
    for (int t = st; t < NT; t += NSTRIPE) {
        int2  iw = siw[t];
        float w  = __int_as_float(iw.y);
        __half2 wh = __float2half2_rn(w);

        const int4* pa = (const int4*)(g_Ch + iw.x + qo);
        int4 Ar = pa[0];
        int4 Br = pa[24];      // next x-row: +192 halves = +384B = +24 int4

        __half2 A0 = int_as_h2(Ar.x), A1 = int_as_h2(Ar.y),
                A2 = int_as_h2(Ar.z), A3 = int_as_h2(Ar.w);
        __half2 B0 = int_as_h2(Br.x), B1 = int_as_h2(Br.y),
                B2 = int_as_h2(Br.z), B3 = int_as_h2(Br.w);

        __half2 r0 = __hfma2(__hsub2(B0, A0), wh, A0);
        __half2 r1 = __hfma2(__hsub2(B1, A1), wh, A1);
        __half2 r2 = __hfma2(__hsub2(B2, A2), wh, A2);
        __half2 r3 = __hfma2(__hsub2(B3, A3), wh, A3);

        float2 f0 = __half22float2(r0);
        float2 f1 = __half22float2(r1);
        float2 f2 = __half22float2(r2);
        float2 f3 = __half22float2(r3);

        float c = srow[t];
        a0 = fmaf(c, f0.x, a0); a1 = fmaf(c, f0.y, a1);
        a2 = fmaf(c, f1.x, a2); a3 = fmaf(c, f1.y, a3);
        a4 = fmaf(c, f2.x, a4); a5 = fmaf(c, f2.y, a5);
        a6 = fmaf(c, f3.x, a6); a7 = fmaf(c, f3.y, a7);
    }

    float* r = red + tid * 8;
    r[0]=a0; r[1]=a1; r[2]=a2; r[3]=a3; r[4]=a4; r[5]=a5; r[6]=a6; r[7]=a7;
    __syncthreads();

    // 48 threads: thread ell sums its T (tables 0..2) and E (table 3) over
    // all stripes, scales, and accumulates Cl terms atomically.
    if (tid < NL) {
        int ell = tid;
        int g   = ell >> 3;
        int j   = ell & 7;
        float sT = 0.f, sE = 0.f;
        #pragma unroll
        for (int sp = 0; sp < NSTRIPE; sp++) {
            const float* base = red + (sp * NQ) * 8 + j;
            sT += base[(0 * 6 + g) * 8] + base[(1 * 6 + g) * 8] + base[(2 * 6 + g) * 8];
            sE += base[(3 * 6 + g) * 8];
        }
        float sc = sscale;
        float T = sT * sc, E = sE * sc;
        atomicAdd(&out[0 * NL + ell], T * T);
        atomicAdd(&out[1 * NL + ell], E * E);
        atomicAdd(&out[2 * NL + ell], T * E);
    }
}

// ---------------------------------------------------------------------------
extern "C" void kernel_launch(void* const* d_in, const int* in_sizes, int n_in,
                              void* d_out, int out_size)
{
    const float* k    = (const float*)d_in[0];
    const float* tau  = (const float*)d_in[1];
    const float* tau0 = (const float*)d_in[2];
    const float* S0   = (const float*)d_in[3];
    const float* S1   = (const float*)d_in[4];
    const float* S2   = (const float*)d_in[5];
    const float* SE   = (const float*)d_in[6];
    const float* bx   = (const float*)d_in[7];
    const float* p0   = (const float*)d_in[8];
    const float* p1   = (const float*)d_in[9];
    const float* p2   = (const float*)d_in[10];
    const float* pe   = (const float*)d_in[11];
    const float* A_s  = (const float*)d_in[12];
    const float* n_s  = (const float*)d_in[13];
    float* out = (float*)d_out;

    kpack<<<(NX * 24) / 256, 256>>>(p0, p1, p2, pe, out);
    klos<<<NK, TPB>>>(k, tau, tau0, bx, S0, S1, S2, SE, A_s, n_s, out);
}